// round 14
// baseline (speedup 1.0000x reference)
#include <cuda_runtime.h>
#include <cuda_fp16.h>
#include <mma.h>
#include <cstdint>

using namespace nvcuda;

#define N_NODES_MAX 50000
#define N_EDGES_MAX 800000
#define D_FEAT 64
#define D_OUT 64
#define N_REL 8
#define KTOT 512          /* k = i*8 + r (matches x row layout) */
#define KCH 64            /* K per chunk */
#define NCHUNKS (KTOT / KCH)
#define MTILE 64
#define TBLOCK 256
#define LDP 72            /* padded row stride in halves (144B) */
#define SCAN_PER 4096
#define TGRID 296         /* transform grid: 2 blocks/SM x 148 */

typedef unsigned long long ull;

// device scratch (static allocation per harness rules)
__device__ __half   g_y[(size_t)N_NODES_MAX * D_OUT];   // 6.4 MB
__device__ __half   g_wt[KTOT * LDP];                   // fused weights, padded
__device__ int      g_cnt[N_NODES_MAX + 64];            // counts/cursors + scan pub tail
__device__ int      g_start[N_NODES_MAX + 1];
__device__ uint32_t g_elist[N_EDGES_MAX];               // src:16 | half(w):16
__device__ int      g_tilectr;                          // dynamic tile counter

// ---------------------------------------------------------------------------
// Wt build + tile-counter init
// ---------------------------------------------------------------------------
extern "C" __global__ void rgcn_wt_build(const float* __restrict__ w_bases,
                                         const float* __restrict__ w_rel,
                                         int tgrid)
{
    int gid = blockIdx.x * blockDim.x + threadIdx.x;
    if (gid == 0) g_tilectr = tgrid;     // same stream as transform: ordered
    if (gid >= KTOT * D_OUT) return;
    int k = gid >> 6;
    int o = gid & 63;
    int i = k >> 3, r = k & 7;
    float acc = 0.f;
    #pragma unroll
    for (int b = 0; b < 4; b++)
        acc += w_rel[r * 4 + b] * w_bases[(b * D_FEAT + i) * D_OUT + o];
    g_wt[k * LDP + o] = __float2half_rn(acc);
}

// ---------------------------------------------------------------------------
// Transform via wmma (HMMA), dynamic 64-row tiles, pipelined conv
// ---------------------------------------------------------------------------
extern "C" __global__ void __launch_bounds__(TBLOCK, 2)
rgcn_transform_mma(const float* __restrict__ x, int n_nodes, int n_tiles)
{
    extern __shared__ __align__(16) char smem[];
    __half* wt_s = (__half*)smem;                        // 512*72 halves
    __half* xb   = (__half*)(smem + KTOT * LDP * 2);     // 2*64*72 halves
    int* tile_s  = (int*)(smem + KTOT * LDP * 2 + 2 * MTILE * LDP * 2);

    const int t = threadIdx.x;
    const int warp = t >> 5;
    const int wm = (warp & 3) * 16;   // row band
    const int wn = (warp >> 2) * 32;  // col half

    {
        const float4* src = (const float4*)g_wt;
        float4* dst = (float4*)wt_s;
        #pragma unroll
        for (int i2 = 0; i2 < 18; i2++) dst[t + i2 * TBLOCK] = src[t + i2 * TBLOCK];
    }

    int tile = blockIdx.x;
    while (tile < n_tiles) {
        const int node0 = tile * MTILE;

        if (t == 0) *tile_s = atomicAdd(&g_tilectr, 1);

        wmma::fragment<wmma::accumulator, 16, 16, 16, float> facc[2];
        wmma::fill_fragment(facc[0], 0.0f);
        wmma::fill_fragment(facc[1], 0.0f);

        float4 pf[4];
        #pragma unroll
        for (int it = 0; it < 4; it++) {
            int f = t + it * TBLOCK;
            int row = f >> 4, c4 = f & 15;
            int node = node0 + row;
            pf[it] = (node < n_nodes)
                ? ((const float4*)x)[(size_t)node * (KTOT / 4) + c4]
                : make_float4(0.f, 0.f, 0.f, 0.f);
        }

        for (int c = 0; c < NCHUNKS; c++) {
            __half* xcur = xb + (c & 1) * (MTILE * LDP);

            #pragma unroll
            for (int it = 0; it < 4; it++) {
                int f = t + it * TBLOCK;
                int row = f >> 4, c4 = f & 15;
                __half2 h0 = __floats2half2_rn(pf[it].x, pf[it].y);
                __half2 h1 = __floats2half2_rn(pf[it].z, pf[it].w);
                uint2 st;
                st.x = *(uint32_t*)&h0;
                st.y = *(uint32_t*)&h1;
                *(uint2*)((char*)xcur + row * (LDP * 2) + c4 * 8) = st;
            }
            __syncthreads();

            if (c + 1 < NCHUNKS) {
                #pragma unroll
                for (int it = 0; it < 4; it++) {
                    int f = t + it * TBLOCK;
                    int row = f >> 4, c4 = f & 15;
                    int node = node0 + row;
                    pf[it] = (node < n_nodes)
                        ? ((const float4*)x)[(size_t)node * (KTOT / 4) + (c + 1) * 16 + c4]
                        : make_float4(0.f, 0.f, 0.f, 0.f);
                }
            }

            #pragma unroll
            for (int kk = 0; kk < 4; kk++) {
                wmma::fragment<wmma::matrix_a, 16, 16, 16, __half, wmma::row_major> fa;
                wmma::load_matrix_sync(fa, xcur + wm * LDP + kk * 16, LDP);
                const __half* wrow = wt_s + (c * KCH + kk * 16) * LDP + wn;
                #pragma unroll
                for (int ni = 0; ni < 2; ni++) {
                    wmma::fragment<wmma::matrix_b, 16, 16, 16, __half, wmma::row_major> fb;
                    wmma::load_matrix_sync(fb, wrow + ni * 16, LDP);
                    wmma::mma_sync(facc[ni], fa, fb, facc[ni]);
                }
            }
        }

        __syncthreads();
        float* stage = (float*)xb;
        #pragma unroll
        for (int ni = 0; ni < 2; ni++)
            wmma::store_matrix_sync(stage + wm * D_OUT + wn + ni * 16,
                                    facc[ni], D_OUT, wmma::mem_row_major);
        __syncthreads();

        #pragma unroll
        for (int it = 0; it < 4; it++) {
            int f = t + it * TBLOCK;
            int row = f >> 4, q = f & 15;
            int node = node0 + row;
            if (node < n_nodes) {
                float4 v = *(const float4*)(stage + row * D_OUT + q * 4);
                __half2 h0 = __floats2half2_rn(v.x, v.y);
                __half2 h1 = __floats2half2_rn(v.z, v.w);
                uint2 st;
                st.x = *(uint32_t*)&h0;
                st.y = *(uint32_t*)&h1;
                *(uint2*)(g_y + (size_t)node * D_OUT + q * 4) = st;
            }
        }
        __syncthreads();
        tile = *tile_s;
    }
}

// ---------------------------------------------------------------------------
// CSR build: one memset -> hist (x4 vectorized) -> fused scan -> fill (x4)
// ---------------------------------------------------------------------------
extern "C" __global__ void rgcn_hist(const int* __restrict__ edst, int n_edges)
{
    int e4 = (blockIdx.x * blockDim.x + threadIdx.x) * 4;
    if (e4 + 3 < n_edges) {
        int4 d = *(const int4*)(edst + e4);
        atomicAdd(&g_cnt[d.x], 1);
        atomicAdd(&g_cnt[d.y], 1);
        atomicAdd(&g_cnt[d.z], 1);
        atomicAdd(&g_cnt[d.w], 1);
    } else {
        for (int e = e4; e < n_edges; e++) atomicAdd(&g_cnt[edst[e]], 1);
    }
}

// single-pass scan, grid <= 16 blocks, parallel publish/poll
extern "C" __global__ void __launch_bounds__(1024, 1)
rgcn_scan_fused(int n_nodes)
{
    __shared__ int wtot[32];
    __shared__ int preds[16];
    __shared__ int bp_sh;
    const int t = threadIdx.x, lane = t & 31, wid = t >> 5;
    const int b = blockIdx.x;
    volatile ull* pub = (volatile ull*)(g_cnt + ((n_nodes + 1) & ~1));

    int base = b * SCAN_PER + t * 4;
    int v[4];
    if (base + 3 < n_nodes) {
        int4 q = *(const int4*)(g_cnt + base);
        v[0] = q.x; v[1] = q.y; v[2] = q.z; v[3] = q.w;
    } else {
        #pragma unroll
        for (int j = 0; j < 4; j++) {
            int idx = base + j;
            v[j] = (idx < n_nodes) ? g_cnt[idx] : 0;
        }
    }
    int tsum = v[0] + v[1] + v[2] + v[3];
    int s = tsum;
    #pragma unroll
    for (int d = 1; d < 32; d <<= 1) {
        int u = __shfl_up_sync(0xffffffffu, s, d);
        if (lane >= d) s += u;
    }
    if (lane == 31) wtot[wid] = s;
    __syncthreads();
    if (wid == 0) {
        int wv = wtot[lane];
        #pragma unroll
        for (int d = 1; d < 32; d <<= 1) {
            int u = __shfl_up_sync(0xffffffffu, wv, d);
            if (lane >= d) wv += u;
        }
        wtot[lane] = wv;
    }
    __syncthreads();
    int local_excl = (s - tsum) + (wid ? wtot[wid - 1] : 0);
    int block_total = wtot[31];

    if (t == 0)
        pub[b] = (1ULL << 32) | (unsigned)block_total;
    if (t < b) {
        ull pv;
        do { pv = pub[t]; } while ((pv >> 32) == 0);
        preds[t] = (int)(unsigned)pv;
    }
    __syncthreads();
    if (t == 0) {
        int r = 0;
        for (int j = 0; j < b; j++) r += preds[j];
        bp_sh = r;
    }
    __syncthreads();

    int off = bp_sh + local_excl;
    #pragma unroll
    for (int j = 0; j < 4; j++) {
        int idx = base + j;
        if (idx < n_nodes) {
            g_start[idx] = off;
            g_cnt[idx]   = off;
            if (idx == n_nodes - 1) g_start[n_nodes] = off + v[j];
            off += v[j];
        }
    }
}

extern "C" __global__ void rgcn_fill(const int*   __restrict__ esrc,
                                     const int*   __restrict__ edst,
                                     const float* __restrict__ ew,
                                     int n_edges)
{
    int e4 = (blockIdx.x * blockDim.x + threadIdx.x) * 4;
    if (e4 + 3 < n_edges) {
        int4   s = *(const int4*)(esrc + e4);
        int4   d = *(const int4*)(edst + e4);
        float4 w = *(const float4*)(ew + e4);
        int sv[4] = {s.x, s.y, s.z, s.w};
        int dv[4] = {d.x, d.y, d.z, d.w};
        float wv[4] = {w.x, w.y, w.z, w.w};
        #pragma unroll
        for (int j = 0; j < 4; j++) {
            int pos = atomicAdd(&g_cnt[dv[j]], 1);
            __half hw = __float2half_rn(wv[j]);
            g_elist[pos] = (uint32_t)sv[j] | ((uint32_t)*(unsigned short*)&hw << 16);
        }
    } else {
        for (int e = e4; e < n_edges; e++) {
            int pos = atomicAdd(&g_cnt[edst[e]], 1);
            __half hw = __float2half_rn(ew[e]);
            g_elist[pos] = (uint32_t)esrc[e] | ((uint32_t)*(unsigned short*)&hw << 16);
        }
    }
}

// ---------------------------------------------------------------------------
// Aggregate: one warp per dst node, half-warps process alternate edges.
// Lane owns 4 outputs (uint2 = 4 halves); shfl_xor(16) combine at end.
// ---------------------------------------------------------------------------
extern "C" __global__ void __launch_bounds__(256, 8)
rgcn_aggregate(float* __restrict__ out, int n_nodes)
{
    int gid = blockIdx.x * blockDim.x + threadIdx.x;
    int n = gid >> 5;
    if (n >= n_nodes) return;
    int lane = gid & 31;
    int half = lane >> 4;
    int l16  = lane & 15;
    int e  = g_start[n];
    int e1 = g_start[n + 1];
    float4 acc = make_float4(0.f, 0.f, 0.f, 0.f);

    // 8 edges per iter: each half-warp handles 4 (alternating), MLP=4 LDG.64
    for (; e + 8 <= e1; e += 8) {
        uint32_t p[4];
        #pragma unroll
        for (int j = 0; j < 4; j++) p[j] = g_elist[e + 2 * j + half];
        uint2 q[4];
        #pragma unroll
        for (int j = 0; j < 4; j++)
            q[j] = *((const uint2*)((const char*)g_y
                     + ((size_t)(p[j] & 0xFFFFu) << 7)) + l16);
        #pragma unroll
        for (int j = 0; j < 4; j++) {
            unsigned short wb = (unsigned short)(p[j] >> 16);
            float w = __half2float(*(__half*)&wb);
            __half2 h0; *(uint32_t*)&h0 = q[j].x;
            __half2 h1; *(uint32_t*)&h1 = q[j].y;
            float2 f0 = __half22float2(h0);
            float2 f1 = __half22float2(h1);
            acc.x += w * f0.x; acc.y += w * f0.y;
            acc.z += w * f1.x; acc.w += w * f1.y;
        }
    }
    // pair tail
    for (; e + 2 <= e1; e += 2) {
        uint32_t p = g_elist[e + half];
        uint2 q = *((const uint2*)((const char*)g_y
                    + ((size_t)(p & 0xFFFFu) << 7)) + l16);
        unsigned short wb = (unsigned short)(p >> 16);
        float w = __half2float(*(__half*)&wb);
        __half2 h0; *(uint32_t*)&h0 = q.x;
        __half2 h1; *(uint32_t*)&h1 = q.y;
        float2 f0 = __half22float2(h0);
        float2 f1 = __half22float2(h1);
        acc.x += w * f0.x; acc.y += w * f0.y;
        acc.z += w * f1.x; acc.w += w * f1.y;
    }
    // odd edge: only half 0 contributes
    if (e < e1 && half == 0) {
        uint32_t p = g_elist[e];
        uint2 q = *((const uint2*)((const char*)g_y
                    + ((size_t)(p & 0xFFFFu) << 7)) + l16);
        unsigned short wb = (unsigned short)(p >> 16);
        float w = __half2float(*(__half*)&wb);
        __half2 h0; *(uint32_t*)&h0 = q.x;
        __half2 h1; *(uint32_t*)&h1 = q.y;
        float2 f0 = __half22float2(h0);
        float2 f1 = __half22float2(h1);
        acc.x += w * f0.x; acc.y += w * f0.y;
        acc.z += w * f1.x; acc.w += w * f1.y;
    }

    // combine halves, lanes 0-15 write float4
    acc.x += __shfl_xor_sync(0xffffffffu, acc.x, 16);
    acc.y += __shfl_xor_sync(0xffffffffu, acc.y, 16);
    acc.z += __shfl_xor_sync(0xffffffffu, acc.z, 16);
    acc.w += __shfl_xor_sync(0xffffffffu, acc.w, 16);
    if (half == 0)
        *(float4*)(out + (size_t)n * D_OUT + l16 * 4) = acc;
}

// ---------------------------------------------------------------------------
extern "C" void kernel_launch(void* const* d_in, const int* in_sizes, int n_in,
                              void* d_out, int out_size)
{
    const float* x    = (const float*)d_in[0];
    const int*   esrc = (const int*)  d_in[1];
    const int*   edst = (const int*)  d_in[2];
    const float* ew   = (const float*)d_in[3];
    const float* wb   = (const float*)d_in[4];
    const float* wrel = (const float*)d_in[5];
    float* out = (float*)d_out;

    const int n_nodes = in_sizes[0] / (D_FEAT * N_REL);
    const int n_edges = in_sizes[1];
    const int n_tiles = (n_nodes + MTILE - 1) / MTILE;
    const int scan_blocks = (n_nodes + SCAN_PER - 1) / SCAN_PER;
    const int tgrid = n_tiles < TGRID ? n_tiles : TGRID;

    const int mma_smem = KTOT * LDP * 2 + 2 * MTILE * LDP * 2 + 16;  // ~92KB
    cudaFuncSetAttribute(rgcn_transform_mma,
                         cudaFuncAttributeMaxDynamicSharedMemorySize, mma_smem);

    // fork stream + events (host-side; outside graph replay cost)
    cudaStream_t s1;
    cudaStreamCreateWithFlags(&s1, cudaStreamNonBlocking);
    cudaEvent_t evFork, evJoin;
    cudaEventCreateWithFlags(&evFork, cudaEventDisableTiming);
    cudaEventCreateWithFlags(&evJoin, cudaEventDisableTiming);

    // branch A (s1): weights + counter init + HMMA transform (dynamic tiles)
    cudaEventRecord(evFork, 0);
    cudaStreamWaitEvent(s1, evFork, 0);
    rgcn_wt_build<<<(KTOT * D_OUT + 255) / 256, 256, 0, s1>>>(wb, wrel, tgrid);
    rgcn_transform_mma<<<tgrid, TBLOCK, mma_smem, s1>>>(x, n_nodes, n_tiles);
    cudaEventRecord(evJoin, s1);

    // branch B (main): CSR build by dst. One memset covers counters + pub tail.
    void* cnt_ptr = nullptr;
    cudaGetSymbolAddress(&cnt_ptr, g_cnt);
    size_t zero_bytes = (size_t)(((n_nodes + 1) & ~1) + 32) * sizeof(int);
    cudaMemsetAsync(cnt_ptr, 0, zero_bytes, 0);

    int e4 = (n_edges + 3) / 4;
    rgcn_hist<<<(e4 + 255) / 256, 256>>>(edst, n_edges);
    rgcn_scan_fused<<<scan_blocks, 1024>>>(n_nodes);
    rgcn_fill<<<(e4 + 255) / 256, 256>>>(esrc, edst, ew, n_edges);

    // join, then gather-aggregate
    cudaStreamWaitEvent(0, evJoin, 0);
    int total_thr = n_nodes * 32;
    rgcn_aggregate<<<(total_thr + 255) / 256, 256>>>(out, n_nodes);
}

// round 15
// speedup vs baseline: 1.0088x; 1.0088x over previous
#include <cuda_runtime.h>
#include <cuda_fp16.h>
#include <mma.h>
#include <cstdint>

using namespace nvcuda;

#define N_NODES_MAX 50000
#define N_EDGES_MAX 800000
#define D_FEAT 64
#define D_OUT 64
#define N_REL 8
#define KTOT 512          /* k = i*8 + r (matches x row layout) */
#define KCH 64            /* K per chunk */
#define NCHUNKS (KTOT / KCH)
#define MTILE 64
#define TBLOCK 256
#define LDP 72            /* padded row stride in halves (144B) */
#define SCAN_PER 4096
#define TGRID 296         /* transform grid: 2 blocks/SM x 148 */

typedef unsigned long long ull;

// device scratch (static allocation per harness rules)
__device__ __half   g_y[(size_t)N_NODES_MAX * D_OUT];   // 6.4 MB
__device__ __half   g_wt[KTOT * LDP];                   // fused weights, padded
__device__ int      g_cnt[N_NODES_MAX + 64];            // counts/cursors + scan pub tail
__device__ int      g_start[N_NODES_MAX + 1];
__device__ uint32_t g_elist[N_EDGES_MAX + 8];           // src:16 | half(w):16 (+pad)
__device__ int      g_tilectr;                          // dynamic tile counter

// ---------------------------------------------------------------------------
// Wt build + tile-counter init
// ---------------------------------------------------------------------------
extern "C" __global__ void rgcn_wt_build(const float* __restrict__ w_bases,
                                         const float* __restrict__ w_rel,
                                         int tgrid)
{
    int gid = blockIdx.x * blockDim.x + threadIdx.x;
    if (gid == 0) g_tilectr = tgrid;     // same stream as transform: ordered
    if (gid >= KTOT * D_OUT) return;
    int k = gid >> 6;
    int o = gid & 63;
    int i = k >> 3, r = k & 7;
    float acc = 0.f;
    #pragma unroll
    for (int b = 0; b < 4; b++)
        acc += w_rel[r * 4 + b] * w_bases[(b * D_FEAT + i) * D_OUT + o];
    g_wt[k * LDP + o] = __float2half_rn(acc);
}

// ---------------------------------------------------------------------------
// Transform via wmma (HMMA), dynamic 64-row tiles, pipelined conv
// ---------------------------------------------------------------------------
extern "C" __global__ void __launch_bounds__(TBLOCK, 2)
rgcn_transform_mma(const float* __restrict__ x, int n_nodes, int n_tiles)
{
    extern __shared__ __align__(16) char smem[];
    __half* wt_s = (__half*)smem;                        // 512*72 halves
    __half* xb   = (__half*)(smem + KTOT * LDP * 2);     // 2*64*72 halves
    int* tile_s  = (int*)(smem + KTOT * LDP * 2 + 2 * MTILE * LDP * 2);

    const int t = threadIdx.x;
    const int warp = t >> 5;
    const int wm = (warp & 3) * 16;   // row band
    const int wn = (warp >> 2) * 32;  // col half

    {
        const float4* src = (const float4*)g_wt;
        float4* dst = (float4*)wt_s;
        #pragma unroll
        for (int i2 = 0; i2 < 18; i2++) dst[t + i2 * TBLOCK] = src[t + i2 * TBLOCK];
    }

    int tile = blockIdx.x;
    while (tile < n_tiles) {
        const int node0 = tile * MTILE;

        if (t == 0) *tile_s = atomicAdd(&g_tilectr, 1);

        wmma::fragment<wmma::accumulator, 16, 16, 16, float> facc[2];
        wmma::fill_fragment(facc[0], 0.0f);
        wmma::fill_fragment(facc[1], 0.0f);

        float4 pf[4];
        #pragma unroll
        for (int it = 0; it < 4; it++) {
            int f = t + it * TBLOCK;
            int row = f >> 4, c4 = f & 15;
            int node = node0 + row;
            pf[it] = (node < n_nodes)
                ? ((const float4*)x)[(size_t)node * (KTOT / 4) + c4]
                : make_float4(0.f, 0.f, 0.f, 0.f);
        }

        for (int c = 0; c < NCHUNKS; c++) {
            __half* xcur = xb + (c & 1) * (MTILE * LDP);

            #pragma unroll
            for (int it = 0; it < 4; it++) {
                int f = t + it * TBLOCK;
                int row = f >> 4, c4 = f & 15;
                __half2 h0 = __floats2half2_rn(pf[it].x, pf[it].y);
                __half2 h1 = __floats2half2_rn(pf[it].z, pf[it].w);
                uint2 st;
                st.x = *(uint32_t*)&h0;
                st.y = *(uint32_t*)&h1;
                *(uint2*)((char*)xcur + row * (LDP * 2) + c4 * 8) = st;
            }
            __syncthreads();

            if (c + 1 < NCHUNKS) {
                #pragma unroll
                for (int it = 0; it < 4; it++) {
                    int f = t + it * TBLOCK;
                    int row = f >> 4, c4 = f & 15;
                    int node = node0 + row;
                    pf[it] = (node < n_nodes)
                        ? ((const float4*)x)[(size_t)node * (KTOT / 4) + (c + 1) * 16 + c4]
                        : make_float4(0.f, 0.f, 0.f, 0.f);
                }
            }

            #pragma unroll
            for (int kk = 0; kk < 4; kk++) {
                wmma::fragment<wmma::matrix_a, 16, 16, 16, __half, wmma::row_major> fa;
                wmma::load_matrix_sync(fa, xcur + wm * LDP + kk * 16, LDP);
                const __half* wrow = wt_s + (c * KCH + kk * 16) * LDP + wn;
                #pragma unroll
                for (int ni = 0; ni < 2; ni++) {
                    wmma::fragment<wmma::matrix_b, 16, 16, 16, __half, wmma::row_major> fb;
                    wmma::load_matrix_sync(fb, wrow + ni * 16, LDP);
                    wmma::mma_sync(facc[ni], fa, fb, facc[ni]);
                }
            }
        }

        __syncthreads();
        float* stage = (float*)xb;
        #pragma unroll
        for (int ni = 0; ni < 2; ni++)
            wmma::store_matrix_sync(stage + wm * D_OUT + wn + ni * 16,
                                    facc[ni], D_OUT, wmma::mem_row_major);
        __syncthreads();

        #pragma unroll
        for (int it = 0; it < 4; it++) {
            int f = t + it * TBLOCK;
            int row = f >> 4, q = f & 15;
            int node = node0 + row;
            if (node < n_nodes) {
                float4 v = *(const float4*)(stage + row * D_OUT + q * 4);
                __half2 h0 = __floats2half2_rn(v.x, v.y);
                __half2 h1 = __floats2half2_rn(v.z, v.w);
                uint2 st;
                st.x = *(uint32_t*)&h0;
                st.y = *(uint32_t*)&h1;
                *(uint2*)(g_y + (size_t)node * D_OUT + q * 4) = st;
            }
        }
        __syncthreads();
        tile = *tile_s;
    }
}

// ---------------------------------------------------------------------------
// CSR build: one memset(g_cnt incl. pub tail) -> hist -> fused scan -> fill
// ---------------------------------------------------------------------------
extern "C" __global__ void rgcn_hist(const int* __restrict__ edst, int n_edges)
{
    int e = blockIdx.x * blockDim.x + threadIdx.x;
    if (e < n_edges) atomicAdd(&g_cnt[edst[e]], 1);
}

// single-pass scan, grid <= 16 blocks, parallel publish/poll
extern "C" __global__ void __launch_bounds__(1024, 1)
rgcn_scan_fused(int n_nodes)
{
    __shared__ int wtot[32];
    __shared__ int preds[16];
    __shared__ int bp_sh;
    const int t = threadIdx.x, lane = t & 31, wid = t >> 5;
    const int b = blockIdx.x;
    volatile ull* pub = (volatile ull*)(g_cnt + ((n_nodes + 1) & ~1));

    int base = b * SCAN_PER + t * 4;
    int v[4];
    if (base + 3 < n_nodes) {
        int4 q = *(const int4*)(g_cnt + base);
        v[0] = q.x; v[1] = q.y; v[2] = q.z; v[3] = q.w;
    } else {
        #pragma unroll
        for (int j = 0; j < 4; j++) {
            int idx = base + j;
            v[j] = (idx < n_nodes) ? g_cnt[idx] : 0;
        }
    }
    int tsum = v[0] + v[1] + v[2] + v[3];
    int s = tsum;
    #pragma unroll
    for (int d = 1; d < 32; d <<= 1) {
        int u = __shfl_up_sync(0xffffffffu, s, d);
        if (lane >= d) s += u;
    }
    if (lane == 31) wtot[wid] = s;
    __syncthreads();
    if (wid == 0) {
        int wv = wtot[lane];
        #pragma unroll
        for (int d = 1; d < 32; d <<= 1) {
            int u = __shfl_up_sync(0xffffffffu, wv, d);
            if (lane >= d) wv += u;
        }
        wtot[lane] = wv;
    }
    __syncthreads();
    int local_excl = (s - tsum) + (wid ? wtot[wid - 1] : 0);
    int block_total = wtot[31];

    if (t == 0)
        pub[b] = (1ULL << 32) | (unsigned)block_total;
    if (t < b) {
        ull pv;
        do { pv = pub[t]; } while ((pv >> 32) == 0);
        preds[t] = (int)(unsigned)pv;
    }
    __syncthreads();
    if (t == 0) {
        int r = 0;
        for (int j = 0; j < b; j++) r += preds[j];
        bp_sh = r;
    }
    __syncthreads();

    int off = bp_sh + local_excl;
    #pragma unroll
    for (int j = 0; j < 4; j++) {
        int idx = base + j;
        if (idx < n_nodes) {
            g_start[idx] = off;
            g_cnt[idx]   = off;
            if (idx == n_nodes - 1) g_start[n_nodes] = off + v[j];
            off += v[j];
        }
    }
}

extern "C" __global__ void rgcn_fill(const int*   __restrict__ esrc,
                                     const int*   __restrict__ edst,
                                     const float* __restrict__ ew,
                                     int n_edges)
{
    int e = blockIdx.x * blockDim.x + threadIdx.x;
    if (e >= n_edges) return;
    int d = edst[e];
    int pos = atomicAdd(&g_cnt[d], 1);
    __half hw = __float2half_rn(ew[e]);
    g_elist[pos] = (uint32_t)esrc[e] | ((uint32_t)*(unsigned short*)&hw << 16);
}

// ---------------------------------------------------------------------------
// Aggregate: one warp per dst node; lane owns 2 outputs. No atomics.
// elist read via uniform LDG.128 after alignment peel (2 issues / 8 edges).
// ---------------------------------------------------------------------------
__device__ __forceinline__ float2 yfrag(uint32_t src, int lane)
{
    unsigned q = *((const unsigned*)g_y + ((size_t)src << 5) + lane);
    __half2 h; *(unsigned*)&h = q;
    return __half22float2(h);
}

__device__ __forceinline__ void acc_edge(float2& acc, uint32_t p, int lane)
{
    float2 f = yfrag(p & 0xFFFFu, lane);
    unsigned short wb = (unsigned short)(p >> 16);
    float w = __half2float(*(__half*)&wb);
    acc.x += w * f.x;
    acc.y += w * f.y;
}

extern "C" __global__ void __launch_bounds__(256, 8)
rgcn_aggregate(float* __restrict__ out, int n_nodes)
{
    int gid = blockIdx.x * blockDim.x + threadIdx.x;
    int n = gid >> 5;
    if (n >= n_nodes) return;
    int lane = gid & 31;
    int e  = g_start[n];
    int e1 = g_start[n + 1];
    float2 acc = make_float2(0.f, 0.f);

    // peel to 16B alignment of elist pointer
    while (e < e1 && (e & 3)) { acc_edge(acc, g_elist[e], lane); e++; }

    // 8 edges per iter via 2 uniform LDG.128 + 8 y loads (MLP=8)
    for (; e + 8 <= e1; e += 8) {
        uint4 a = *(const uint4*)(g_elist + e);
        uint4 b = *(const uint4*)(g_elist + e + 4);
        uint32_t p[8] = {a.x, a.y, a.z, a.w, b.x, b.y, b.z, b.w};
        float2 f[8];
        #pragma unroll
        for (int j = 0; j < 8; j++) f[j] = yfrag(p[j] & 0xFFFFu, lane);
        #pragma unroll
        for (int j = 0; j < 8; j++) {
            unsigned short wb = (unsigned short)(p[j] >> 16);
            float w = __half2float(*(__half*)&wb);
            acc.x += w * f[j].x;
            acc.y += w * f[j].y;
        }
    }
    if (e + 4 <= e1) {
        uint4 a = *(const uint4*)(g_elist + e);
        uint32_t p[4] = {a.x, a.y, a.z, a.w};
        float2 f[4];
        #pragma unroll
        for (int j = 0; j < 4; j++) f[j] = yfrag(p[j] & 0xFFFFu, lane);
        #pragma unroll
        for (int j = 0; j < 4; j++) {
            unsigned short wb = (unsigned short)(p[j] >> 16);
            float w = __half2float(*(__half*)&wb);
            acc.x += w * f[j].x;
            acc.y += w * f[j].y;
        }
        e += 4;
    }
    for (; e < e1; e++) acc_edge(acc, g_elist[e], lane);

    *(float2*)(out + (size_t)n * D_OUT + lane * 2) = acc;
}

// ---------------------------------------------------------------------------
extern "C" void kernel_launch(void* const* d_in, const int* in_sizes, int n_in,
                              void* d_out, int out_size)
{
    const float* x    = (const float*)d_in[0];
    const int*   esrc = (const int*)  d_in[1];
    const int*   edst = (const int*)  d_in[2];
    const float* ew   = (const float*)d_in[3];
    const float* wb   = (const float*)d_in[4];
    const float* wrel = (const float*)d_in[5];
    float* out = (float*)d_out;

    const int n_nodes = in_sizes[0] / (D_FEAT * N_REL);
    const int n_edges = in_sizes[1];
    const int n_tiles = (n_nodes + MTILE - 1) / MTILE;
    const int scan_blocks = (n_nodes + SCAN_PER - 1) / SCAN_PER;
    const int tgrid = n_tiles < TGRID ? n_tiles : TGRID;

    const int mma_smem = KTOT * LDP * 2 + 2 * MTILE * LDP * 2 + 16;  // ~92KB
    cudaFuncSetAttribute(rgcn_transform_mma,
                         cudaFuncAttributeMaxDynamicSharedMemorySize, mma_smem);

    // fork stream + events (host-side; outside graph replay cost)
    cudaStream_t s1;
    cudaStreamCreateWithFlags(&s1, cudaStreamNonBlocking);
    cudaEvent_t evFork, evJoin;
    cudaEventCreateWithFlags(&evFork, cudaEventDisableTiming);
    cudaEventCreateWithFlags(&evJoin, cudaEventDisableTiming);

    // branch A (s1): weights + counter init + HMMA transform (dynamic tiles)
    cudaEventRecord(evFork, 0);
    cudaStreamWaitEvent(s1, evFork, 0);
    rgcn_wt_build<<<(KTOT * D_OUT + 255) / 256, 256, 0, s1>>>(wb, wrel, tgrid);
    rgcn_transform_mma<<<tgrid, TBLOCK, mma_smem, s1>>>(x, n_nodes, n_tiles);
    cudaEventRecord(evJoin, s1);

    // branch B (main): CSR build by dst. One memset covers counters + pub tail.
    void* cnt_ptr = nullptr;
    cudaGetSymbolAddress(&cnt_ptr, g_cnt);
    size_t zero_bytes = (size_t)(((n_nodes + 1) & ~1) + 32) * sizeof(int);
    cudaMemsetAsync(cnt_ptr, 0, zero_bytes, 0);

    rgcn_hist<<<(n_edges + 255) / 256, 256>>>(edst, n_edges);
    rgcn_scan_fused<<<scan_blocks, 1024>>>(n_nodes);
    rgcn_fill<<<(n_edges + 255) / 256, 256>>>(esrc, edst, ew, n_edges);

    // join, then gather-aggregate
    cudaStreamWaitEvent(0, evJoin, 0);
    int total_thr = n_nodes * 32;
    rgcn_aggregate<<<(total_thr + 255) / 256, 256>>>(out, n_nodes);
}

// round 16
// speedup vs baseline: 1.0102x; 1.0014x over previous
#include <cuda_runtime.h>
#include <cuda_fp16.h>
#include <mma.h>
#include <cstdint>

using namespace nvcuda;

#define N_NODES_MAX 50000
#define N_EDGES_MAX 800000
#define D_FEAT 64
#define D_OUT 64
#define N_REL 8
#define KTOT 512          /* k = i*8 + r (matches x row layout) */
#define KCH 64            /* K per chunk */
#define NCHUNKS (KTOT / KCH)
#define MTILE 64
#define TBLOCK 256
#define LDP 72            /* padded row stride in halves (144B) */
#define SCAN_PER 4096
#define TGRID 296         /* transform grid: 2 blocks/SM x 148 */

typedef unsigned long long ull;

// device scratch (static allocation per harness rules)
__device__ __half   g_y[(size_t)N_NODES_MAX * D_OUT];   // 6.4 MB
__device__ __half   g_wt[KTOT * LDP];                   // fused weights, padded
__device__ int      g_cnt[N_NODES_MAX + 64];            // counts/cursors + scan pub tail
__device__ int      g_start[N_NODES_MAX + 1];
__device__ uint32_t g_elist[N_EDGES_MAX];               // src:16 | half(w):16
__device__ int      g_tilectr;                          // dynamic tile counter

// ---------------------------------------------------------------------------
// Wt build + tile-counter init
// ---------------------------------------------------------------------------
extern "C" __global__ void rgcn_wt_build(const float* __restrict__ w_bases,
                                         const float* __restrict__ w_rel,
                                         int tgrid)
{
    int gid = blockIdx.x * blockDim.x + threadIdx.x;
    if (gid == 0) g_tilectr = tgrid;     // same stream as transform: ordered
    if (gid >= KTOT * D_OUT) return;
    int k = gid >> 6;
    int o = gid & 63;
    int i = k >> 3, r = k & 7;
    float acc = 0.f;
    #pragma unroll
    for (int b = 0; b < 4; b++)
        acc += w_rel[r * 4 + b] * w_bases[(b * D_FEAT + i) * D_OUT + o];
    g_wt[k * LDP + o] = __float2half_rn(acc);
}

// ---------------------------------------------------------------------------
// Transform via wmma (HMMA), dynamic 64-row tiles, pipelined conv
// ---------------------------------------------------------------------------
extern "C" __global__ void __launch_bounds__(TBLOCK, 2)
rgcn_transform_mma(const float* __restrict__ x, int n_nodes, int n_tiles)
{
    extern __shared__ __align__(16) char smem[];
    __half* wt_s = (__half*)smem;                        // 512*72 halves
    __half* xb   = (__half*)(smem + KTOT * LDP * 2);     // 2*64*72 halves
    int* tile_s  = (int*)(smem + KTOT * LDP * 2 + 2 * MTILE * LDP * 2);

    const int t = threadIdx.x;
    const int warp = t >> 5;
    const int wm = (warp & 3) * 16;   // row band
    const int wn = (warp >> 2) * 32;  // col half

    {
        const float4* src = (const float4*)g_wt;
        float4* dst = (float4*)wt_s;
        #pragma unroll
        for (int i2 = 0; i2 < 18; i2++) dst[t + i2 * TBLOCK] = src[t + i2 * TBLOCK];
    }

    int tile = blockIdx.x;
    while (tile < n_tiles) {
        const int node0 = tile * MTILE;

        if (t == 0) *tile_s = atomicAdd(&g_tilectr, 1);

        wmma::fragment<wmma::accumulator, 16, 16, 16, float> facc[2];
        wmma::fill_fragment(facc[0], 0.0f);
        wmma::fill_fragment(facc[1], 0.0f);

        float4 pf[4];
        #pragma unroll
        for (int it = 0; it < 4; it++) {
            int f = t + it * TBLOCK;
            int row = f >> 4, c4 = f & 15;
            int node = node0 + row;
            pf[it] = (node < n_nodes)
                ? ((const float4*)x)[(size_t)node * (KTOT / 4) + c4]
                : make_float4(0.f, 0.f, 0.f, 0.f);
        }

        for (int c = 0; c < NCHUNKS; c++) {
            __half* xcur = xb + (c & 1) * (MTILE * LDP);

            #pragma unroll
            for (int it = 0; it < 4; it++) {
                int f = t + it * TBLOCK;
                int row = f >> 4, c4 = f & 15;
                __half2 h0 = __floats2half2_rn(pf[it].x, pf[it].y);
                __half2 h1 = __floats2half2_rn(pf[it].z, pf[it].w);
                uint2 st;
                st.x = *(uint32_t*)&h0;
                st.y = *(uint32_t*)&h1;
                *(uint2*)((char*)xcur + row * (LDP * 2) + c4 * 8) = st;
            }
            __syncthreads();

            if (c + 1 < NCHUNKS) {
                #pragma unroll
                for (int it = 0; it < 4; it++) {
                    int f = t + it * TBLOCK;
                    int row = f >> 4, c4 = f & 15;
                    int node = node0 + row;
                    pf[it] = (node < n_nodes)
                        ? ((const float4*)x)[(size_t)node * (KTOT / 4) + (c + 1) * 16 + c4]
                        : make_float4(0.f, 0.f, 0.f, 0.f);
                }
            }

            #pragma unroll
            for (int kk = 0; kk < 4; kk++) {
                wmma::fragment<wmma::matrix_a, 16, 16, 16, __half, wmma::row_major> fa;
                wmma::load_matrix_sync(fa, xcur + wm * LDP + kk * 16, LDP);
                const __half* wrow = wt_s + (c * KCH + kk * 16) * LDP + wn;
                #pragma unroll
                for (int ni = 0; ni < 2; ni++) {
                    wmma::fragment<wmma::matrix_b, 16, 16, 16, __half, wmma::row_major> fb;
                    wmma::load_matrix_sync(fb, wrow + ni * 16, LDP);
                    wmma::mma_sync(facc[ni], fa, fb, facc[ni]);
                }
            }
        }

        __syncthreads();
        float* stage = (float*)xb;
        #pragma unroll
        for (int ni = 0; ni < 2; ni++)
            wmma::store_matrix_sync(stage + wm * D_OUT + wn + ni * 16,
                                    facc[ni], D_OUT, wmma::mem_row_major);
        __syncthreads();

        #pragma unroll
        for (int it = 0; it < 4; it++) {
            int f = t + it * TBLOCK;
            int row = f >> 4, q = f & 15;
            int node = node0 + row;
            if (node < n_nodes) {
                float4 v = *(const float4*)(stage + row * D_OUT + q * 4);
                __half2 h0 = __floats2half2_rn(v.x, v.y);
                __half2 h1 = __floats2half2_rn(v.z, v.w);
                uint2 st;
                st.x = *(uint32_t*)&h0;
                st.y = *(uint32_t*)&h1;
                *(uint2*)(g_y + (size_t)node * D_OUT + q * 4) = st;
            }
        }
        __syncthreads();
        tile = *tile_s;
    }
}

// ---------------------------------------------------------------------------
// CSR build: one memset(g_cnt incl. pub tail) -> hist -> fused scan -> fill
// ---------------------------------------------------------------------------
extern "C" __global__ void rgcn_hist(const int* __restrict__ edst, int n_edges)
{
    int e = blockIdx.x * blockDim.x + threadIdx.x;
    if (e < n_edges) atomicAdd(&g_cnt[edst[e]], 1);
}

// single-pass scan, grid <= 16 blocks, parallel publish/poll
extern "C" __global__ void __launch_bounds__(1024, 1)
rgcn_scan_fused(int n_nodes)
{
    __shared__ int wtot[32];
    __shared__ int preds[16];
    __shared__ int bp_sh;
    const int t = threadIdx.x, lane = t & 31, wid = t >> 5;
    const int b = blockIdx.x;
    volatile ull* pub = (volatile ull*)(g_cnt + ((n_nodes + 1) & ~1));

    int base = b * SCAN_PER + t * 4;
    int v[4];
    if (base + 3 < n_nodes) {
        int4 q = *(const int4*)(g_cnt + base);
        v[0] = q.x; v[1] = q.y; v[2] = q.z; v[3] = q.w;
    } else {
        #pragma unroll
        for (int j = 0; j < 4; j++) {
            int idx = base + j;
            v[j] = (idx < n_nodes) ? g_cnt[idx] : 0;
        }
    }
    int tsum = v[0] + v[1] + v[2] + v[3];
    int s = tsum;
    #pragma unroll
    for (int d = 1; d < 32; d <<= 1) {
        int u = __shfl_up_sync(0xffffffffu, s, d);
        if (lane >= d) s += u;
    }
    if (lane == 31) wtot[wid] = s;
    __syncthreads();
    if (wid == 0) {
        int wv = wtot[lane];
        #pragma unroll
        for (int d = 1; d < 32; d <<= 1) {
            int u = __shfl_up_sync(0xffffffffu, wv, d);
            if (lane >= d) wv += u;
        }
        wtot[lane] = wv;
    }
    __syncthreads();
    int local_excl = (s - tsum) + (wid ? wtot[wid - 1] : 0);
    int block_total = wtot[31];

    if (t == 0)
        pub[b] = (1ULL << 32) | (unsigned)block_total;
    if (t < b) {
        ull pv;
        do { pv = pub[t]; } while ((pv >> 32) == 0);
        preds[t] = (int)(unsigned)pv;
    }
    __syncthreads();
    if (t == 0) {
        int r = 0;
        for (int j = 0; j < b; j++) r += preds[j];
        bp_sh = r;
    }
    __syncthreads();

    int off = bp_sh + local_excl;
    #pragma unroll
    for (int j = 0; j < 4; j++) {
        int idx = base + j;
        if (idx < n_nodes) {
            g_start[idx] = off;
            g_cnt[idx]   = off;
            if (idx == n_nodes - 1) g_start[n_nodes] = off + v[j];
            off += v[j];
        }
    }
}

extern "C" __global__ void rgcn_fill(const int*   __restrict__ esrc,
                                     const int*   __restrict__ edst,
                                     const float* __restrict__ ew,
                                     int n_edges)
{
    int e = blockIdx.x * blockDim.x + threadIdx.x;
    if (e >= n_edges) return;
    int d = edst[e];
    int pos = atomicAdd(&g_cnt[d], 1);
    __half hw = __float2half_rn(ew[e]);
    g_elist[pos] = (uint32_t)esrc[e] | ((uint32_t)*(unsigned short*)&hw << 16);
}

// ---------------------------------------------------------------------------
// Aggregate: one warp per dst node; lane owns 2 outputs. No atomics.
// elist staged through smem via coalesced loads -> y loads are the only
// global-latency chain (1 L2 round-trip per 8-edge batch instead of 2).
// ---------------------------------------------------------------------------
__device__ __forceinline__ float2 yfrag(uint32_t src, int lane)
{
    unsigned q = *((const unsigned*)g_y + ((size_t)src << 5) + lane);
    __half2 h; *(unsigned*)&h = q;
    return __half22float2(h);
}

__device__ __forceinline__ void acc_edge(float2& acc, uint32_t p, int lane)
{
    float2 f = yfrag(p & 0xFFFFu, lane);
    unsigned short wb = (unsigned short)(p >> 16);
    float w = __half2float(*(__half*)&wb);
    acc.x += w * f.x;
    acc.y += w * f.y;
}

extern "C" __global__ void __launch_bounds__(256, 8)
rgcn_aggregate(float* __restrict__ out, int n_nodes)
{
    __shared__ uint32_t sbuf[8][64];
    int gid = blockIdx.x * blockDim.x + threadIdx.x;
    int n = gid >> 5;
    if (n >= n_nodes) return;        // warp-uniform exit
    int lane = gid & 31;
    int warp = threadIdx.x >> 5;
    int e  = g_start[n];
    int e1 = g_start[n + 1];
    float2 acc = make_float2(0.f, 0.f);

    while (e < e1) {
        int chunk = e1 - e;
        if (chunk > 64) chunk = 64;

        // coalesced cooperative elist load into smem (<=2 LDG per warp)
        if (lane < chunk)      sbuf[warp][lane]      = g_elist[e + lane];
        if (lane + 32 < chunk) sbuf[warp][lane + 32] = g_elist[e + lane + 32];
        __syncwarp();

        int j = 0;
        for (; j + 8 <= chunk; j += 8) {
            uint32_t p[8];
            #pragma unroll
            for (int k = 0; k < 8; k++) p[k] = sbuf[warp][j + k];
            float2 f[8];
            #pragma unroll
            for (int k = 0; k < 8; k++) f[k] = yfrag(p[k] & 0xFFFFu, lane);
            #pragma unroll
            for (int k = 0; k < 8; k++) {
                unsigned short wb = (unsigned short)(p[k] >> 16);
                float w = __half2float(*(__half*)&wb);
                acc.x += w * f[k].x;
                acc.y += w * f[k].y;
            }
        }
        if (j + 4 <= chunk) {
            uint32_t p[4];
            #pragma unroll
            for (int k = 0; k < 4; k++) p[k] = sbuf[warp][j + k];
            float2 f[4];
            #pragma unroll
            for (int k = 0; k < 4; k++) f[k] = yfrag(p[k] & 0xFFFFu, lane);
            #pragma unroll
            for (int k = 0; k < 4; k++) {
                unsigned short wb = (unsigned short)(p[k] >> 16);
                float w = __half2float(*(__half*)&wb);
                acc.x += w * f[k].x;
                acc.y += w * f[k].y;
            }
            j += 4;
        }
        for (; j < chunk; j++) acc_edge(acc, sbuf[warp][j], lane);

        e += chunk;
        __syncwarp();   // all lanes done reading sbuf before next chunk refill
    }

    *(float2*)(out + (size_t)n * D_OUT + lane * 2) = acc;
}

// ---------------------------------------------------------------------------
extern "C" void kernel_launch(void* const* d_in, const int* in_sizes, int n_in,
                              void* d_out, int out_size)
{
    const float* x    = (const float*)d_in[0];
    const int*   esrc = (const int*)  d_in[1];
    const int*   edst = (const int*)  d_in[2];
    const float* ew   = (const float*)d_in[3];
    const float* wb   = (const float*)d_in[4];
    const float* wrel = (const float*)d_in[5];
    float* out = (float*)d_out;

    const int n_nodes = in_sizes[0] / (D_FEAT * N_REL);
    const int n_edges = in_sizes[1];
    const int n_tiles = (n_nodes + MTILE - 1) / MTILE;
    const int scan_blocks = (n_nodes + SCAN_PER - 1) / SCAN_PER;
    const int tgrid = n_tiles < TGRID ? n_tiles : TGRID;

    const int mma_smem = KTOT * LDP * 2 + 2 * MTILE * LDP * 2 + 16;  // ~92KB
    cudaFuncSetAttribute(rgcn_transform_mma,
                         cudaFuncAttributeMaxDynamicSharedMemorySize, mma_smem);

    // fork stream + events (host-side; outside graph replay cost)
    cudaStream_t s1;
    cudaStreamCreateWithFlags(&s1, cudaStreamNonBlocking);
    cudaEvent_t evFork, evJoin;
    cudaEventCreateWithFlags(&evFork, cudaEventDisableTiming);
    cudaEventCreateWithFlags(&evJoin, cudaEventDisableTiming);

    // branch A (s1): weights + counter init + HMMA transform (dynamic tiles)
    cudaEventRecord(evFork, 0);
    cudaStreamWaitEvent(s1, evFork, 0);
    rgcn_wt_build<<<(KTOT * D_OUT + 255) / 256, 256, 0, s1>>>(wb, wrel, tgrid);
    rgcn_transform_mma<<<tgrid, TBLOCK, mma_smem, s1>>>(x, n_nodes, n_tiles);
    cudaEventRecord(evJoin, s1);

    // branch B (main): CSR build by dst. One memset covers counters + pub tail.
    void* cnt_ptr = nullptr;
    cudaGetSymbolAddress(&cnt_ptr, g_cnt);
    size_t zero_bytes = (size_t)(((n_nodes + 1) & ~1) + 32) * sizeof(int);
    cudaMemsetAsync(cnt_ptr, 0, zero_bytes, 0);

    rgcn_hist<<<(n_edges + 255) / 256, 256>>>(edst, n_edges);
    rgcn_scan_fused<<<scan_blocks, 1024>>>(n_nodes);
    rgcn_fill<<<(n_edges + 255) / 256, 256>>>(esrc, edst, ew, n_edges);

    // join, then gather-aggregate
    cudaStreamWaitEvent(0, evJoin, 0);
    int total_thr = n_nodes * 32;
    rgcn_aggregate<<<(total_thr + 255) / 256, 256>>>(out, n_nodes);
}

// round 17
// speedup vs baseline: 1.0202x; 1.0099x over previous
#include <cuda_runtime.h>
#include <cuda_fp16.h>
#include <mma.h>
#include <cstdint>

using namespace nvcuda;

#define N_NODES_MAX 50000
#define N_EDGES_MAX 800000
#define D_FEAT 64
#define D_OUT 64
#define N_REL 8
#define KTOT 512          /* k = i*8 + r (matches x row layout) */
#define KCH 64            /* K per chunk */
#define NCHUNKS (KTOT / KCH)
#define MTILE 64
#define TBLOCK 256
#define LDP 72            /* padded row stride in halves (144B) */
#define SCAN_PER 4096
#define TGRID 296         /* transform grid: 2 blocks/SM x 148 */

typedef unsigned long long ull;

// device scratch (static allocation; zero-initialized at module load.
// The pipeline is SELF-CLEANING: aggregate restores g_cnt (incl. scan pub
// tail) to all-zeros each run, so no memset is needed per launch.)
__device__ __half   g_y[(size_t)N_NODES_MAX * D_OUT];   // 6.4 MB
__device__ __half   g_wt[KTOT * LDP];                   // fused weights, padded
__device__ int      g_cnt[N_NODES_MAX + 64];            // counts/cursors + scan pub tail
__device__ int      g_start[N_NODES_MAX + 1];
__device__ uint32_t g_elist[N_EDGES_MAX];               // src:16 | half(w):16
__device__ int      g_tilectr;                          // dynamic tile counter

// ---------------------------------------------------------------------------
// Wt build + tile-counter init
// ---------------------------------------------------------------------------
extern "C" __global__ void rgcn_wt_build(const float* __restrict__ w_bases,
                                         const float* __restrict__ w_rel,
                                         int tgrid)
{
    int gid = blockIdx.x * blockDim.x + threadIdx.x;
    if (gid == 0) g_tilectr = tgrid;     // same stream as transform: ordered
    if (gid >= KTOT * D_OUT) return;
    int k = gid >> 6;
    int o = gid & 63;
    int i = k >> 3, r = k & 7;
    float acc = 0.f;
    #pragma unroll
    for (int b = 0; b < 4; b++)
        acc += w_rel[r * 4 + b] * w_bases[(b * D_FEAT + i) * D_OUT + o];
    g_wt[k * LDP + o] = __float2half_rn(acc);
}

// ---------------------------------------------------------------------------
// Transform via wmma (HMMA), dynamic 64-row tiles, pipelined conv
// ---------------------------------------------------------------------------
extern "C" __global__ void __launch_bounds__(TBLOCK, 2)
rgcn_transform_mma(const float* __restrict__ x, int n_nodes, int n_tiles)
{
    extern __shared__ __align__(16) char smem[];
    __half* wt_s = (__half*)smem;                        // 512*72 halves
    __half* xb   = (__half*)(smem + KTOT * LDP * 2);     // 2*64*72 halves
    int* tile_s  = (int*)(smem + KTOT * LDP * 2 + 2 * MTILE * LDP * 2);

    const int t = threadIdx.x;
    const int warp = t >> 5;
    const int wm = (warp & 3) * 16;   // row band
    const int wn = (warp >> 2) * 32;  // col half

    {
        const float4* src = (const float4*)g_wt;
        float4* dst = (float4*)wt_s;
        #pragma unroll
        for (int i2 = 0; i2 < 18; i2++) dst[t + i2 * TBLOCK] = src[t + i2 * TBLOCK];
    }

    int tile = blockIdx.x;
    while (tile < n_tiles) {
        const int node0 = tile * MTILE;

        if (t == 0) *tile_s = atomicAdd(&g_tilectr, 1);

        wmma::fragment<wmma::accumulator, 16, 16, 16, float> facc[2];
        wmma::fill_fragment(facc[0], 0.0f);
        wmma::fill_fragment(facc[1], 0.0f);

        float4 pf[4];
        #pragma unroll
        for (int it = 0; it < 4; it++) {
            int f = t + it * TBLOCK;
            int row = f >> 4, c4 = f & 15;
            int node = node0 + row;
            pf[it] = (node < n_nodes)
                ? ((const float4*)x)[(size_t)node * (KTOT / 4) + c4]
                : make_float4(0.f, 0.f, 0.f, 0.f);
        }

        for (int c = 0; c < NCHUNKS; c++) {
            __half* xcur = xb + (c & 1) * (MTILE * LDP);

            #pragma unroll
            for (int it = 0; it < 4; it++) {
                int f = t + it * TBLOCK;
                int row = f >> 4, c4 = f & 15;
                __half2 h0 = __floats2half2_rn(pf[it].x, pf[it].y);
                __half2 h1 = __floats2half2_rn(pf[it].z, pf[it].w);
                uint2 st;
                st.x = *(uint32_t*)&h0;
                st.y = *(uint32_t*)&h1;
                *(uint2*)((char*)xcur + row * (LDP * 2) + c4 * 8) = st;
            }
            __syncthreads();

            if (c + 1 < NCHUNKS) {
                #pragma unroll
                for (int it = 0; it < 4; it++) {
                    int f = t + it * TBLOCK;
                    int row = f >> 4, c4 = f & 15;
                    int node = node0 + row;
                    pf[it] = (node < n_nodes)
                        ? ((const float4*)x)[(size_t)node * (KTOT / 4) + (c + 1) * 16 + c4]
                        : make_float4(0.f, 0.f, 0.f, 0.f);
                }
            }

            #pragma unroll
            for (int kk = 0; kk < 4; kk++) {
                wmma::fragment<wmma::matrix_a, 16, 16, 16, __half, wmma::row_major> fa;
                wmma::load_matrix_sync(fa, xcur + wm * LDP + kk * 16, LDP);
                const __half* wrow = wt_s + (c * KCH + kk * 16) * LDP + wn;
                #pragma unroll
                for (int ni = 0; ni < 2; ni++) {
                    wmma::fragment<wmma::matrix_b, 16, 16, 16, __half, wmma::row_major> fb;
                    wmma::load_matrix_sync(fb, wrow + ni * 16, LDP);
                    wmma::mma_sync(facc[ni], fa, fb, facc[ni]);
                }
            }
        }

        __syncthreads();
        float* stage = (float*)xb;
        #pragma unroll
        for (int ni = 0; ni < 2; ni++)
            wmma::store_matrix_sync(stage + wm * D_OUT + wn + ni * 16,
                                    facc[ni], D_OUT, wmma::mem_row_major);
        __syncthreads();

        #pragma unroll
        for (int it = 0; it < 4; it++) {
            int f = t + it * TBLOCK;
            int row = f >> 4, q = f & 15;
            int node = node0 + row;
            if (node < n_nodes) {
                float4 v = *(const float4*)(stage + row * D_OUT + q * 4);
                __half2 h0 = __floats2half2_rn(v.x, v.y);
                __half2 h1 = __floats2half2_rn(v.z, v.w);
                uint2 st;
                st.x = *(uint32_t*)&h0;
                st.y = *(uint32_t*)&h1;
                *(uint2*)(g_y + (size_t)node * D_OUT + q * 4) = st;
            }
        }
        __syncthreads();
        tile = *tile_s;
    }
}

// ---------------------------------------------------------------------------
// CSR build: hist -> fused scan -> fill  (g_cnt arrives zeroed; see above)
// ---------------------------------------------------------------------------
extern "C" __global__ void rgcn_hist(const int* __restrict__ edst, int n_edges)
{
    int e = blockIdx.x * blockDim.x + threadIdx.x;
    if (e < n_edges) atomicAdd(&g_cnt[edst[e]], 1);
}

// single-pass scan, grid <= 16 blocks, parallel publish/poll
extern "C" __global__ void __launch_bounds__(1024, 1)
rgcn_scan_fused(int n_nodes)
{
    __shared__ int wtot[32];
    __shared__ int preds[16];
    __shared__ int bp_sh;
    const int t = threadIdx.x, lane = t & 31, wid = t >> 5;
    const int b = blockIdx.x;
    volatile ull* pub = (volatile ull*)(g_cnt + ((n_nodes + 1) & ~1));

    int base = b * SCAN_PER + t * 4;
    int v[4];
    if (base + 3 < n_nodes) {
        int4 q = *(const int4*)(g_cnt + base);
        v[0] = q.x; v[1] = q.y; v[2] = q.z; v[3] = q.w;
    } else {
        #pragma unroll
        for (int j = 0; j < 4; j++) {
            int idx = base + j;
            v[j] = (idx < n_nodes) ? g_cnt[idx] : 0;
        }
    }
    int tsum = v[0] + v[1] + v[2] + v[3];
    int s = tsum;
    #pragma unroll
    for (int d = 1; d < 32; d <<= 1) {
        int u = __shfl_up_sync(0xffffffffu, s, d);
        if (lane >= d) s += u;
    }
    if (lane == 31) wtot[wid] = s;
    __syncthreads();
    if (wid == 0) {
        int wv = wtot[lane];
        #pragma unroll
        for (int d = 1; d < 32; d <<= 1) {
            int u = __shfl_up_sync(0xffffffffu, wv, d);
            if (lane >= d) wv += u;
        }
        wtot[lane] = wv;
    }
    __syncthreads();
    int local_excl = (s - tsum) + (wid ? wtot[wid - 1] : 0);
    int block_total = wtot[31];

    if (t == 0)
        pub[b] = (1ULL << 32) | (unsigned)block_total;
    if (t < b) {
        ull pv;
        do { pv = pub[t]; } while ((pv >> 32) == 0);
        preds[t] = (int)(unsigned)pv;
    }
    __syncthreads();
    if (t == 0) {
        int r = 0;
        for (int j = 0; j < b; j++) r += preds[j];
        bp_sh = r;
    }
    __syncthreads();

    int off = bp_sh + local_excl;
    #pragma unroll
    for (int j = 0; j < 4; j++) {
        int idx = base + j;
        if (idx < n_nodes) {
            g_start[idx] = off;
            g_cnt[idx]   = off;
            if (idx == n_nodes - 1) g_start[n_nodes] = off + v[j];
            off += v[j];
        }
    }
}

extern "C" __global__ void rgcn_fill(const int*   __restrict__ esrc,
                                     const int*   __restrict__ edst,
                                     const float* __restrict__ ew,
                                     int n_edges)
{
    int e = blockIdx.x * blockDim.x + threadIdx.x;
    if (e >= n_edges) return;
    int d = edst[e];
    int pos = atomicAdd(&g_cnt[d], 1);
    __half hw = __float2half_rn(ew[e]);
    g_elist[pos] = (uint32_t)esrc[e] | ((uint32_t)*(unsigned short*)&hw << 16);
}

// ---------------------------------------------------------------------------
// Aggregate (R13 loop): one warp per dst node; lane owns 2 outputs.
// Also self-cleans g_cnt (counters + scan pub tail) back to zero for the
// next replay, replacing the per-launch memset.
// ---------------------------------------------------------------------------
__device__ __forceinline__ float2 yfrag(uint32_t src, int lane)
{
    unsigned q = *((const unsigned*)g_y + ((size_t)src << 5) + lane);
    __half2 h; *(unsigned*)&h = q;
    return __half22float2(h);
}

extern "C" __global__ void __launch_bounds__(256, 8)
rgcn_aggregate(float* __restrict__ out, int n_nodes)
{
    int gid = blockIdx.x * blockDim.x + threadIdx.x;
    // reset the scan publish tail (32 ints after aligned n_nodes+1)
    if (gid < 32) g_cnt[((n_nodes + 1) & ~1) + gid] = 0;
    int n = gid >> 5;
    if (n >= n_nodes) return;
    int lane = gid & 31;
    int e  = g_start[n];
    int e1 = g_start[n + 1];
    if (lane == 0) g_cnt[n] = 0;    // reset cursor -> count slot for next run
    float2 acc = make_float2(0.f, 0.f);

    for (; e + 8 <= e1; e += 8) {
        uint32_t p[8];
        #pragma unroll
        for (int j = 0; j < 8; j++) p[j] = g_elist[e + j];
        float2 f[8];
        #pragma unroll
        for (int j = 0; j < 8; j++) f[j] = yfrag(p[j] & 0xFFFFu, lane);
        #pragma unroll
        for (int j = 0; j < 8; j++) {
            unsigned short wb = (unsigned short)(p[j] >> 16);
            float w = __half2float(*(__half*)&wb);
            acc.x += w * f[j].x;
            acc.y += w * f[j].y;
        }
    }
    if (e + 4 <= e1) {
        uint32_t p[4];
        #pragma unroll
        for (int j = 0; j < 4; j++) p[j] = g_elist[e + j];
        float2 f[4];
        #pragma unroll
        for (int j = 0; j < 4; j++) f[j] = yfrag(p[j] & 0xFFFFu, lane);
        #pragma unroll
        for (int j = 0; j < 4; j++) {
            unsigned short wb = (unsigned short)(p[j] >> 16);
            float w = __half2float(*(__half*)&wb);
            acc.x += w * f[j].x;
            acc.y += w * f[j].y;
        }
        e += 4;
    }
    for (; e < e1; e++) {
        uint32_t p = g_elist[e];
        float2 f = yfrag(p & 0xFFFFu, lane);
        unsigned short wb = (unsigned short)(p >> 16);
        float w = __half2float(*(__half*)&wb);
        acc.x += w * f.x;
        acc.y += w * f.y;
    }
    *(float2*)(out + (size_t)n * D_OUT + lane * 2) = acc;
}

// ---------------------------------------------------------------------------
extern "C" void kernel_launch(void* const* d_in, const int* in_sizes, int n_in,
                              void* d_out, int out_size)
{
    const float* x    = (const float*)d_in[0];
    const int*   esrc = (const int*)  d_in[1];
    const int*   edst = (const int*)  d_in[2];
    const float* ew   = (const float*)d_in[3];
    const float* wb   = (const float*)d_in[4];
    const float* wrel = (const float*)d_in[5];
    float* out = (float*)d_out;

    const int n_nodes = in_sizes[0] / (D_FEAT * N_REL);
    const int n_edges = in_sizes[1];
    const int n_tiles = (n_nodes + MTILE - 1) / MTILE;
    const int scan_blocks = (n_nodes + SCAN_PER - 1) / SCAN_PER;
    const int tgrid = n_tiles < TGRID ? n_tiles : TGRID;

    const int mma_smem = KTOT * LDP * 2 + 2 * MTILE * LDP * 2 + 16;  // ~92KB
    cudaFuncSetAttribute(rgcn_transform_mma,
                         cudaFuncAttributeMaxDynamicSharedMemorySize, mma_smem);

    // fork stream + events (host-side; outside graph replay cost)
    cudaStream_t s1;
    cudaStreamCreateWithFlags(&s1, cudaStreamNonBlocking);
    cudaEvent_t evFork, evJoin;
    cudaEventCreateWithFlags(&evFork, cudaEventDisableTiming);
    cudaEventCreateWithFlags(&evJoin, cudaEventDisableTiming);

    // branch A (s1): weights + counter init + HMMA transform (dynamic tiles)
    cudaEventRecord(evFork, 0);
    cudaStreamWaitEvent(s1, evFork, 0);
    rgcn_wt_build<<<(KTOT * D_OUT + 255) / 256, 256, 0, s1>>>(wb, wrel, tgrid);
    rgcn_transform_mma<<<tgrid, TBLOCK, mma_smem, s1>>>(x, n_nodes, n_tiles);
    cudaEventRecord(evJoin, s1);

    // branch B (main): CSR build by dst (g_cnt pre-zeroed by prior run /
    // module load; aggregate re-zeroes it at the end of this run)
    rgcn_hist<<<(n_edges + 255) / 256, 256>>>(edst, n_edges);
    rgcn_scan_fused<<<scan_blocks, 1024>>>(n_nodes);
    rgcn_fill<<<(n_edges + 255) / 256, 256>>>(esrc, edst, ew, n_edges);

    // join, then gather-aggregate (also self-cleans g_cnt)
    cudaStreamWaitEvent(0, evJoin, 0);
    int total_thr = n_nodes * 32;
    rgcn_aggregate<<<(total_thr + 255) / 256, 256>>>(out, n_nodes);
}